// round 16
// baseline (speedup 1.0000x reference)
// NodeModel GNN block — HMMA bf16 3-term split, fragment-reuse build (r15b)
#include <cuda_runtime.h>
#include <cuda_bf16.h>
#include <cstdint>

#define NN 50000
#define NE 500000
#define DD 256
#define KW 512

// ---------------- static device scratch ----------------
__device__ __align__(16) float g_xa_buf[(size_t)NN * DD];   // x @ W1a + b1
__device__ __align__(16) float g_agg_buf[(size_t)NN * DD];  // scatter-sum
__device__ float g_deg[NN];                                 // counts -> 1/max(cnt,1)
// weights transposed to [w][n][k] bf16, hi and lo parts (w: 0=W1, 1=W2)
__device__ __align__(16) unsigned short g_w_hi[2u * 256u * KW];
__device__ __align__(16) unsigned short g_w_lo[2u * 256u * KW];

// ---------------- helpers ----------------
static __device__ __forceinline__ uint32_t to_smem_u32(const void* p) {
    uint32_t a;
    asm("{ .reg .u64 t; cvta.to.shared.u64 t, %1; cvt.u32.u64 %0, t; }" : "=r"(a) : "l"(p));
    return a;
}
static __device__ __forceinline__ uint32_t bfpack2(__nv_bfloat16 a, __nv_bfloat16 b) {
    return (uint32_t)__bfloat16_as_ushort(a) | ((uint32_t)__bfloat16_as_ushort(b) << 16);
}

#define LDSMX4(r0, r1, r2, r3, addr)                                         \
    asm volatile("ldmatrix.sync.aligned.m8n8.x4.shared.b16 {%0,%1,%2,%3}, [%4];" \
                 : "=r"(r0), "=r"(r1), "=r"(r2), "=r"(r3) : "r"(addr))

#define HMMA16816(d, a, b0, b1)                                              \
    asm volatile("mma.sync.aligned.m16n8k16.row.col.f32.bf16.bf16.f32 "      \
                 "{%0,%1,%2,%3},{%4,%5,%6,%7},{%8,%9},{%0,%1,%2,%3};"        \
                 : "+f"((d)[0]), "+f"((d)[1]), "+f"((d)[2]), "+f"((d)[3])    \
                 : "r"((a)[0]), "r"((a)[1]), "r"((a)[2]), "r"((a)[3]),       \
                   "r"(b0), "r"(b1))

// ---------------- setup kernels ----------------
__global__ void clear_buffers() {
    int stride = gridDim.x * blockDim.x;
    int tid = blockIdx.x * blockDim.x + threadIdx.x;
    for (int i = tid; i < NN * DD; i += stride) g_agg_buf[i] = 0.0f;
    for (int i = tid; i < NN; i += stride) g_deg[i] = 0.0f;
}
__global__ void invert_counts() {
    int i = blockIdx.x * blockDim.x + threadIdx.x;
    if (i < NN) g_deg[i] = 1.0f / fmaxf(g_deg[i], 1.0f);
}
// W[k][n] f32 -> [n][k] bf16 hi/lo transposed images
__global__ void weight_prep(const float* __restrict__ W1, const float* __restrict__ W2) {
    int t = blockIdx.x * blockDim.x + threadIdx.x;
    if (t >= 2 * 64 * 256) return;
    int n = t & 255;
    int k0 = ((t >> 8) & 63) * 8;
    int w = t >> 14;
    const float* W = w ? W2 : W1;
#pragma unroll
    for (int i = 0; i < 8; i++) {
        int k = k0 + i;
        float v = W[(size_t)k * DD + n];
        __nv_bfloat16 h = __float2bfloat16(v);
        float r = v - __bfloat162float(h);
        size_t o = ((size_t)w * 256 + n) * KW + k;
        g_w_hi[o] = __bfloat16_as_ushort(h);
        g_w_lo[o] = __bfloat16_as_ushort(__float2bfloat16(r));
    }
}

// ---------------- HMMA GEMM core ----------------
// CTA tile 128(M) x 128(N); gridDim.x = 2 N-halves (fast-varying -> L2 A-reuse)
// Single smem stage per plane; A/B fragments loaded once, reused across the
// three bf16 split products (AhiBhi + AhiBlo + AloBhi).
// MODE 0: g_xa = x @ W1a + b1                                 (M=NN, K=256)
// MODE 1: h = relu(ea @ W1b + g_xa[row]); red into g_agg[col] (M=NE, K=256)
// MODE 2: out = relu(x @ W2a + (agg*rinv) @ W2b + b2)         (M=NN, K=512)
template <int MODE>
__global__ __launch_bounds__(256, 2)
void gemm_core(const float* __restrict__ x, const float* __restrict__ ea,
               const int* __restrict__ eidx, const float* __restrict__ bias,
               float* __restrict__ outp)
{
    __shared__ __align__(16) unsigned char shA[2][4096];  // [hi/lo][128x16 bf16 swz]
    __shared__ __align__(16) unsigned char shB[2][4096];
    __shared__ int e_src[128], e_dst[128];
    __shared__ float s_rinv[128];

    const int tid = threadIdx.x, lane = tid & 31, wid = tid >> 5;
    const int wm = wid >> 1, wn = wid & 1;   // 4(M) x 2(N) warps, warp tile 32x64
    const int n0 = blockIdx.x * 128;
    const int m0 = blockIdx.y * 128;

    if (MODE == 1 && tid < 128) {
        int e = min(m0 + tid, NE - 1);
        e_src[tid] = eidx[e];
        e_dst[tid] = eidx[NE + e];
    }
    if (MODE == 2 && tid < 128) {
        int m = m0 + tid;
        s_rinv[tid] = (m < NN) ? g_deg[m] : 0.0f;
    }

    const uint32_t baseA[2] = { to_smem_u32(shA[0]), to_smem_u32(shA[1]) };
    const uint32_t baseB[2] = { to_smem_u32(shB[0]), to_smem_u32(shB[1]) };

    float4 stageA[2];
    uint4  stageB[2];

    auto fetch = [&](int ks) {
#pragma unroll
        for (int j = 0; j < 2; j++) {
            int idx = tid + j * 256;
            int row = idx >> 2, kk = idx & 3;
            if (MODE == 1) {
                int gm = min(m0 + row, NE - 1);
                stageA[j] = *(const float4*)&ea[(size_t)gm * DD + ks * 16 + kk * 4];
            } else if (MODE == 0) {
                int gm = min(m0 + row, NN - 1);
                stageA[j] = *(const float4*)&x[(size_t)gm * DD + ks * 16 + kk * 4];
            } else {
                int gm = min(m0 + row, NN - 1);
                if (ks < 16) {
                    stageA[j] = *(const float4*)&x[(size_t)gm * DD + ks * 16 + kk * 4];
                } else {
                    float4 v = *(const float4*)&g_agg_buf[(size_t)gm * DD + (ks - 16) * 16 + kk * 4];
                    float s = s_rinv[row];
                    v.x *= s; v.y *= s; v.z *= s; v.w *= s;
                    stageA[j] = v;
                }
            }
        }
        const int w  = (MODE == 2) ? 1 : 0;
        const int kb = (MODE == 1) ? 256 + ks * 16 : ks * 16;
        {
            int n = tid >> 1, c = tid & 1;
            size_t o = ((size_t)w * 256 + n0 + n) * KW + kb + c * 8;
            stageB[0] = *(const uint4*)&g_w_hi[o];
            stageB[1] = *(const uint4*)&g_w_lo[o];
        }
    };
    auto commit = [&]() {
#pragma unroll
        for (int j = 0; j < 2; j++) {
            int idx = tid + j * 256;
            int row = idx >> 2, kk = idx & 3;
            int c = kk >> 1;
            uint32_t off = row * 32 + (((c ^ ((row >> 2) & 1)) << 4)) + (kk & 1) * 8;
            float4 v = stageA[j];
            __nv_bfloat16 h0 = __float2bfloat16(v.x), h1 = __float2bfloat16(v.y);
            __nv_bfloat16 h2 = __float2bfloat16(v.z), h3 = __float2bfloat16(v.w);
            __nv_bfloat16 l0 = __float2bfloat16(v.x - __bfloat162float(h0));
            __nv_bfloat16 l1 = __float2bfloat16(v.y - __bfloat162float(h1));
            __nv_bfloat16 l2 = __float2bfloat16(v.z - __bfloat162float(h2));
            __nv_bfloat16 l3 = __float2bfloat16(v.w - __bfloat162float(h3));
            *(uint2*)(shA[0] + off) = make_uint2(bfpack2(h0, h1), bfpack2(h2, h3));
            *(uint2*)(shA[1] + off) = make_uint2(bfpack2(l0, l1), bfpack2(l2, l3));
        }
        {
            int n = tid >> 1, c = tid & 1;
            uint32_t off = n * 32 + ((c ^ ((n >> 2) & 1)) << 4);
            *(uint4*)(shB[0] + off) = stageB[0];
            *(uint4*)(shB[1] + off) = stageB[1];
        }
    };

    float acc[2][8][4];
#pragma unroll
    for (int a = 0; a < 2; a++)
#pragma unroll
        for (int b = 0; b < 8; b++)
#pragma unroll
            for (int q = 0; q < 4; q++) acc[a][b][q] = 0.0f;

    auto mac_step = [&]() {
        uint32_t aH[2][4], aL[2][4];
#pragma unroll
        for (int mi = 0; mi < 2; mi++) {
            int row = wm * 32 + mi * 16 + (lane & 7) + ((lane >> 3) & 1) * 8;
            int c = lane >> 4;
            uint32_t off = row * 32 + ((c ^ ((row >> 2) & 1)) << 4);
            LDSMX4(aH[mi][0], aH[mi][1], aH[mi][2], aH[mi][3], baseA[0] + off);
            LDSMX4(aL[mi][0], aL[mi][1], aL[mi][2], aL[mi][3], baseA[1] + off);
        }
#pragma unroll
        for (int np = 0; np < 4; np++) {
            int n = wn * 64 + np * 16 + (lane & 7) + ((lane >> 4) & 1) * 8;
            int c = (lane >> 3) & 1;
            uint32_t off = n * 32 + ((c ^ ((n >> 2) & 1)) << 4);
            uint32_t bH[4], bL[4];
            LDSMX4(bH[0], bH[1], bH[2], bH[3], baseB[0] + off);
            LDSMX4(bL[0], bL[1], bL[2], bL[3], baseB[1] + off);
#pragma unroll
            for (int mi = 0; mi < 2; mi++) {
                HMMA16816(acc[mi][np * 2 + 0], aH[mi], bH[0], bH[1]);
                HMMA16816(acc[mi][np * 2 + 1], aH[mi], bH[2], bH[3]);
                HMMA16816(acc[mi][np * 2 + 0], aH[mi], bL[0], bL[1]);
                HMMA16816(acc[mi][np * 2 + 1], aH[mi], bL[2], bL[3]);
                HMMA16816(acc[mi][np * 2 + 0], aL[mi], bH[0], bH[1]);
                HMMA16816(acc[mi][np * 2 + 1], aL[mi], bH[2], bH[3]);
            }
        }
    };

    const int NK = (MODE == 2) ? 32 : 16;
    fetch(0);
    for (int ks = 0; ks < NK; ks++) {
        commit();
        __syncthreads();
        if (ks + 1 < NK) fetch(ks + 1);
        mac_step();
        __syncthreads();
    }

    // ---------------- epilogue ----------------
    const int colb = n0 + wn * 64 + (lane & 3) * 2;
    if (MODE == 1) {
#pragma unroll
        for (int mi = 0; mi < 2; mi++) {
#pragma unroll
            for (int h = 0; h < 2; h++) {
                int lr = wm * 32 + mi * 16 + (lane >> 2) + h * 8;
                bool valid = (m0 + lr < NE);
                if (!valid) continue;
                int srcr = e_src[lr], dstc = e_dst[lr];
                const float* xr = &g_xa_buf[(size_t)srcr * DD];
                float* ag = &g_agg_buf[(size_t)dstc * DD];
#pragma unroll
                for (int nt = 0; nt < 8; nt++) {
                    int n = colb + nt * 8;
                    float2 xv = *(const float2*)&xr[n];
                    float v0 = fmaxf(acc[mi][nt][h * 2 + 0] + xv.x, 0.0f);
                    float v1 = fmaxf(acc[mi][nt][h * 2 + 1] + xv.y, 0.0f);
                    asm volatile("red.global.add.v2.f32 [%0], {%1,%2};"
                                 :: "l"(ag + n), "f"(v0), "f"(v1) : "memory");
                }
            }
        }
        if (blockIdx.x == 0 && tid < 128 && m0 + tid < NE)
            atomicAdd(&g_deg[e_dst[tid]], 1.0f);
    } else {
#pragma unroll
        for (int mi = 0; mi < 2; mi++) {
#pragma unroll
            for (int h = 0; h < 2; h++) {
                int row = m0 + wm * 32 + mi * 16 + (lane >> 2) + h * 8;
                if (row >= NN) continue;
                float* dst = (MODE == 0) ? &g_xa_buf[(size_t)row * DD] : &outp[(size_t)row * DD];
#pragma unroll
                for (int nt = 0; nt < 8; nt++) {
                    int n = colb + nt * 8;
                    float2 bb = *(const float2*)&bias[n];
                    float2 v;
                    v.x = acc[mi][nt][h * 2 + 0] + bb.x;
                    v.y = acc[mi][nt][h * 2 + 1] + bb.y;
                    if (MODE == 2) { v.x = fmaxf(v.x, 0.0f); v.y = fmaxf(v.y, 0.0f); }
                    *(float2*)&dst[n] = v;
                }
            }
        }
    }
}

// ---------------------------------------------------------------------------
extern "C" void kernel_launch(void* const* d_in, const int* in_sizes, int n_in,
                              void* d_out, int out_size) {
    const float* x  = (const float*)d_in[0];
    const int* eix  = (const int*)d_in[1];   // int32 (jax x64 disabled)
    const float* ea = (const float*)d_in[2];
    const float* W1 = (const float*)d_in[5];
    const float* b1 = (const float*)d_in[6];
    const float* W2 = (const float*)d_in[7];
    const float* b2 = (const float*)d_in[8];
    float* out      = (float*)d_out;
    (void)in_sizes; (void)n_in; (void)out_size;

    clear_buffers<<<2048, 256>>>();
    weight_prep<<<128, 256>>>(W1, W2);
    dim3 gN(2, (NN + 127) / 128);
    dim3 gE(2, (NE + 127) / 128);
    gemm_core<0><<<gN, 256>>>(x, ea, eix, b1, nullptr);
    gemm_core<1><<<gE, 256>>>(x, ea, eix, b1, nullptr);
    invert_counts<<<(NN + 255) / 256, 256>>>();
    gemm_core<2><<<gN, 256>>>(x, ea, eix, b2, out);
}